// round 1
// baseline (speedup 1.0000x reference)
#include <cuda_runtime.h>

// SSConv2d: per-pixel input-group routed 3x3 conv (64 oc total) + maxout group
// selection. B=derived, H=W=256, Cin=16, IN_GROUPS=OUT_GROUPS=4, Cout=16.
//
// Strategy: block computes a 32x8 output tile. Input pixels (incl. halo) are
// bucketed by in-group g once. For each (tap, g), per-thread weight sub-slice
// (16c x 4oc) is held in registers packed as f32x2 pairs over c; x streams from
// shared memory; partial dot accumulated in registers, then one float4 RMW into
// a padded smem accumulator tile (exclusive ownership within a tap; barrier
// between taps => race free and deterministic).

#define TX 32
#define TY 8
#define NPIX (TX * TY)      // 256
#define IN_W 34
#define IN_H 10
#define NIN (IN_W * IN_H)   // 340
#define ACC_STRIDE 68       // floats per accumulator row (68 = 4*17, conflict-free)
#define NTHREADS 256

typedef unsigned long long ull;

// reordered weights: [tap(9)][g(4)][c(16)][oc(64)]
__device__ float g_wr[9 * 4 * 16 * 64];

__global__ void reorder_w_kernel(const float* __restrict__ w) {
    int i = blockIdx.x * blockDim.x + threadIdx.x;
    if (i >= 9 * 4 * 16 * 64) return;
    int oc  = i & 63;
    int c   = (i >> 6) & 15;
    int g   = (i >> 10) & 3;
    int tap = i >> 12;
    // weight layout: [oc][ic=g*16+c][ky][kx], tap = ky*3+kx
    g_wr[i] = w[(oc * 64 + g * 16 + c) * 9 + tap];
}

__device__ __forceinline__ ull pack2(float lo, float hi) {
    ull r;
    asm("mov.b64 %0, {%1, %2};" : "=l"(r) : "f"(lo), "f"(hi));
    return r;
}
__device__ __forceinline__ void unpack2(float& lo, float& hi, ull v) {
    asm("mov.b64 {%0, %1}, %2;" : "=f"(lo), "=f"(hi) : "l"(v));
}
__device__ __forceinline__ ull fma2(ull a, ull b, ull c) {
    ull d;
    asm("fma.rn.f32x2 %0, %1, %2, %3;" : "=l"(d) : "l"(a), "l"(b), "l"(c));
    return d;
}
__device__ __forceinline__ ull mul2(ull a, ull b) {
    ull d;
    asm("mul.rn.f32x2 %0, %1, %2;" : "=l"(d) : "l"(a), "l"(b));
    return d;
}

// smem layout (floats):
//   x_s   : NIN*16                    = 5440
//   acc_s : NPIX*ACC_STRIDE           = 17408
//   w_s   : 4*16*64                   = 4096
//   then  : ushort list[4][NIN] (2720 B) + int cnt[4] (16 B)
#define SMEM_FLOATS (NIN * 16 + NPIX * ACC_STRIDE + 4096)
#define SMEM_BYTES (SMEM_FLOATS * 4 + 4 * NIN * 2 + 16)

extern __shared__ float smem_dyn[];

__global__ __launch_bounds__(NTHREADS, 2)
void ssconv_main(const float* __restrict__ x, const int* __restrict__ gidx,
                 const float* __restrict__ bias, float* __restrict__ out,
                 float* __restrict__ out_idx, int write_idx) {
    float* x_s = smem_dyn;
    float* acc_s = x_s + NIN * 16;
    float* w_s = acc_s + NPIX * ACC_STRIDE;
    unsigned short* list_s = (unsigned short*)(w_s + 4096);
    int* cnt_s = (int*)(list_s + 4 * NIN);

    const int t = threadIdx.x;
    const int b = blockIdx.z;
    const int oy0 = blockIdx.y * TY;
    const int ox0 = blockIdx.x * TX;

    if (t < 4) cnt_s[t] = 0;
    __syncthreads();

    // ---- load input tile (with halo) into smem; OOB pixels stay unused ----
    for (int f = t; f < NIN * 4; f += NTHREADS) {
        int p = f >> 2, c4 = f & 3;
        int ly = p / IN_W, lx = p - ly * IN_W;
        int iy = oy0 - 1 + ly, ix = ox0 - 1 + lx;
        float4 v = make_float4(0.f, 0.f, 0.f, 0.f);
        if ((unsigned)iy < 256u && (unsigned)ix < 256u)
            v = *(const float4*)(x + (((size_t)b * 256 + iy) * 256 + ix) * 16 + c4 * 4);
        *(float4*)(x_s + p * 16 + c4 * 4) = v;
    }
    // ---- classify input pixels into g-buckets ----
    for (int p = t; p < NIN; p += NTHREADS) {
        int ly = p / IN_W, lx = p - ly * IN_W;
        int iy = oy0 - 1 + ly, ix = ox0 - 1 + lx;
        if ((unsigned)iy < 256u && (unsigned)ix < 256u) {
            int g = gidx[((size_t)b * 256 + iy) * 256 + ix];
            int pos = atomicAdd(&cnt_s[g], 1);
            list_s[g * NIN + pos] = (unsigned short)((ly << 6) | lx);
        }
    }
    // ---- init accumulators to bias ----
    for (int f = t; f < NPIX * 17; f += NTHREADS) {
        int c4 = f % 17;
        float4 v = make_float4(0.f, 0.f, 0.f, 0.f);
        if (c4 < 16) v = *(const float4*)(bias + c4 * 4);
        ((float4*)acc_s)[f] = v;
    }
    __syncthreads();

    const int ocg = t & 15;   // 16 groups of 4 consecutive out-channels
    const int slot = t >> 4;  // 16 parallel slots over the pixel list

#pragma unroll 1
    for (int tap = 0; tap < 9; tap++) {
        const int ky = tap / 3;
        const int kx = tap - ky * 3;
        // stage this tap's weights (all 4 groups, 16KB) into smem
        for (int f = t; f < 1024; f += NTHREADS)
            ((float4*)w_s)[f] = ((const float4*)g_wr)[tap * 1024 + f];
        __syncthreads();

#pragma unroll 1
        for (int g = 0; g < 4; g++) {
            // pack weights for this (tap, g): 4 oc lanes x 8 c-pairs
            ull wp0[8], wp1[8], wp2[8], wp3[8];
            const float* wb = w_s + g * 1024 + ocg * 4;
#pragma unroll
            for (int c2 = 0; c2 < 8; c2++) {
                float4 u = *(const float4*)(wb + (2 * c2) * 64);
                float4 v = *(const float4*)(wb + (2 * c2 + 1) * 64);
                wp0[c2] = pack2(u.x, v.x);
                wp1[c2] = pack2(u.y, v.y);
                wp2[c2] = pack2(u.z, v.z);
                wp3[c2] = pack2(u.w, v.w);
            }
            const int cnt = cnt_s[g];
            for (int i = slot; i < cnt; i += 16) {
                int pk = list_s[g * NIN + i];
                int ly = pk >> 6, lx = pk & 63;
                int oy = ly - ky, ox = lx - kx;
                if ((unsigned)oy < (unsigned)TY && (unsigned)ox < (unsigned)TX) {
                    const ull* xp = (const ull*)(x_s + (ly * IN_W + lx) * 16);
                    ull xv = xp[0];
                    ull a0 = mul2(wp0[0], xv);
                    ull a1 = mul2(wp1[0], xv);
                    ull a2 = mul2(wp2[0], xv);
                    ull a3 = mul2(wp3[0], xv);
#pragma unroll
                    for (int c2 = 1; c2 < 8; c2++) {
                        xv = xp[c2];
                        a0 = fma2(wp0[c2], xv, a0);
                        a1 = fma2(wp1[c2], xv, a1);
                        a2 = fma2(wp2[c2], xv, a2);
                        a3 = fma2(wp3[c2], xv, a3);
                    }
                    float l0, h0, l1, h1, l2, h2, l3, h3;
                    unpack2(l0, h0, a0);
                    unpack2(l1, h1, a1);
                    unpack2(l2, h2, a2);
                    unpack2(l3, h3, a3);
                    float4* ap = (float4*)(acc_s + (oy * TX + ox) * ACC_STRIDE + ocg * 4);
                    float4 av = *ap;
                    av.x += l0 + h0;
                    av.y += l1 + h1;
                    av.z += l2 + h2;
                    av.w += l3 + h3;
                    *ap = av;
                }
            }
        }
        __syncthreads();
    }

    // ---- epilogue: maxout group selection, one thread per pixel ----
    {
        const float* ar = acc_s + t * ACC_STRIDE;
        float best = -3.4e38f;
        int bi = 0;
#pragma unroll
        for (int og = 0; og < 4; og++) {
            float m = -3.4e38f;
#pragma unroll
            for (int k = 0; k < 16; k += 4) {
                float4 v = *(const float4*)(ar + og * 16 + k);
                m = fmaxf(m, fmaxf(fmaxf(v.x, v.y), fmaxf(v.z, v.w)));
            }
            if (m > best) { best = m; bi = og; }  // first-max tie-break (jnp.argmax)
        }
        int pyl = t >> 5, pxl = t & 31;
        size_t opix = ((size_t)b * 256 + (oy0 + pyl)) * 256 + (ox0 + pxl);
        float4* op = (float4*)(out + opix * 16);
        const float4* sp = (const float4*)(ar + bi * 16);
        op[0] = sp[0];
        op[1] = sp[1];
        op[2] = sp[2];
        op[3] = sp[3];
        if (write_idx) out_idx[opix] = (float)bi;
    }
}

extern "C" void kernel_launch(void* const* d_in, const int* in_sizes, int n_in,
                              void* d_out, int out_size) {
    const float* x = (const float*)d_in[0];
    const int* gi = (const int*)d_in[1];
    const float* w = (const float*)d_in[2];
    const float* bias = (const float*)d_in[3];
    float* out = (float*)d_out;

    const int n_sel = in_sizes[0];            // B*H*W*16 (sel output size)
    const int n_pix = in_sizes[1];            // B*H*W
    const int B = n_pix / (256 * 256);
    const int write_idx = (out_size >= n_sel + n_pix) ? 1 : 0;

    reorder_w_kernel<<<(9 * 4 * 16 * 64 + 255) / 256, 256>>>(w);

    cudaFuncSetAttribute(ssconv_main, cudaFuncAttributeMaxDynamicSharedMemorySize,
                         SMEM_BYTES);
    dim3 grid(256 / TX, 256 / TY, B);
    ssconv_main<<<grid, NTHREADS, SMEM_BYTES>>>(x, gi, bias, out, out + n_sel,
                                                write_idx);
}

// round 2
// speedup vs baseline: 1.0010x; 1.0010x over previous
#include <cuda_runtime.h>

// SSConv2d: per-pixel input-group routed 3x3 conv (64 oc total) + maxout group
// selection. B=derived, H=W=256, Cin=16, IN_GROUPS=OUT_GROUPS=4, Cout=16.
//
// Strategy: block computes a 32x8 output tile. Input pixels (incl. halo) are
// bucketed by in-group g once. For each (tap, g), per-thread weight sub-slice
// (16c x 4oc) is held in registers packed as f32x2 pairs over c; x streams from
// shared memory; partial dot accumulated in registers, then one float4 RMW into
// a padded smem accumulator tile (exclusive ownership within a tap; barrier
// between taps => race free and deterministic).

#define TX 32
#define TY 8
#define NPIX (TX * TY)      // 256
#define IN_W 34
#define IN_H 10
#define NIN (IN_W * IN_H)   // 340
#define ACC_STRIDE 68       // floats per accumulator row (68 = 4*17, conflict-free)
#define NTHREADS 256

typedef unsigned long long ull;

// reordered weights: [tap(9)][g(4)][c(16)][oc(64)]
__device__ float g_wr[9 * 4 * 16 * 64];

__global__ void reorder_w_kernel(const float* __restrict__ w) {
    int i = blockIdx.x * blockDim.x + threadIdx.x;
    if (i >= 9 * 4 * 16 * 64) return;
    int oc  = i & 63;
    int c   = (i >> 6) & 15;
    int g   = (i >> 10) & 3;
    int tap = i >> 12;
    // weight layout: [oc][ic=g*16+c][ky][kx], tap = ky*3+kx
    g_wr[i] = w[(oc * 64 + g * 16 + c) * 9 + tap];
}

__device__ __forceinline__ ull pack2(float lo, float hi) {
    ull r;
    asm("mov.b64 %0, {%1, %2};" : "=l"(r) : "f"(lo), "f"(hi));
    return r;
}
__device__ __forceinline__ void unpack2(float& lo, float& hi, ull v) {
    asm("mov.b64 {%0, %1}, %2;" : "=f"(lo), "=f"(hi) : "l"(v));
}
__device__ __forceinline__ ull fma2(ull a, ull b, ull c) {
    ull d;
    asm("fma.rn.f32x2 %0, %1, %2, %3;" : "=l"(d) : "l"(a), "l"(b), "l"(c));
    return d;
}
__device__ __forceinline__ ull mul2(ull a, ull b) {
    ull d;
    asm("mul.rn.f32x2 %0, %1, %2;" : "=l"(d) : "l"(a), "l"(b));
    return d;
}

// smem layout (floats):
//   x_s   : NIN*16                    = 5440
//   acc_s : NPIX*ACC_STRIDE           = 17408
//   w_s   : 4*16*64                   = 4096
//   then  : ushort list[4][NIN] (2720 B) + int cnt[4] (16 B)
#define SMEM_FLOATS (NIN * 16 + NPIX * ACC_STRIDE + 4096)
#define SMEM_BYTES (SMEM_FLOATS * 4 + 4 * NIN * 2 + 16)

extern __shared__ float smem_dyn[];

__global__ __launch_bounds__(NTHREADS, 2)
void ssconv_main(const float* __restrict__ x, const int* __restrict__ gidx,
                 const float* __restrict__ bias, float* __restrict__ out,
                 float* __restrict__ out_idx, int write_idx) {
    float* x_s = smem_dyn;
    float* acc_s = x_s + NIN * 16;
    float* w_s = acc_s + NPIX * ACC_STRIDE;
    unsigned short* list_s = (unsigned short*)(w_s + 4096);
    int* cnt_s = (int*)(list_s + 4 * NIN);

    const int t = threadIdx.x;
    const int b = blockIdx.z;
    const int oy0 = blockIdx.y * TY;
    const int ox0 = blockIdx.x * TX;

    if (t < 4) cnt_s[t] = 0;
    __syncthreads();

    // ---- load input tile (with halo) into smem; OOB pixels stay unused ----
    for (int f = t; f < NIN * 4; f += NTHREADS) {
        int p = f >> 2, c4 = f & 3;
        int ly = p / IN_W, lx = p - ly * IN_W;
        int iy = oy0 - 1 + ly, ix = ox0 - 1 + lx;
        float4 v = make_float4(0.f, 0.f, 0.f, 0.f);
        if ((unsigned)iy < 256u && (unsigned)ix < 256u)
            v = *(const float4*)(x + (((size_t)b * 256 + iy) * 256 + ix) * 16 + c4 * 4);
        *(float4*)(x_s + p * 16 + c4 * 4) = v;
    }
    // ---- classify input pixels into g-buckets ----
    for (int p = t; p < NIN; p += NTHREADS) {
        int ly = p / IN_W, lx = p - ly * IN_W;
        int iy = oy0 - 1 + ly, ix = ox0 - 1 + lx;
        if ((unsigned)iy < 256u && (unsigned)ix < 256u) {
            int g = gidx[((size_t)b * 256 + iy) * 256 + ix];
            int pos = atomicAdd(&cnt_s[g], 1);
            list_s[g * NIN + pos] = (unsigned short)((ly << 6) | lx);
        }
    }
    // ---- init accumulators to bias ----
    for (int f = t; f < NPIX * 17; f += NTHREADS) {
        int c4 = f % 17;
        float4 v = make_float4(0.f, 0.f, 0.f, 0.f);
        if (c4 < 16) v = *(const float4*)(bias + c4 * 4);
        ((float4*)acc_s)[f] = v;
    }
    __syncthreads();

    const int ocg = t & 15;   // 16 groups of 4 consecutive out-channels
    const int slot = t >> 4;  // 16 parallel slots over the pixel list

#pragma unroll 1
    for (int tap = 0; tap < 9; tap++) {
        const int ky = tap / 3;
        const int kx = tap - ky * 3;
        // stage this tap's weights (all 4 groups, 16KB) into smem
        for (int f = t; f < 1024; f += NTHREADS)
            ((float4*)w_s)[f] = ((const float4*)g_wr)[tap * 1024 + f];
        __syncthreads();

#pragma unroll 1
        for (int g = 0; g < 4; g++) {
            // pack weights for this (tap, g): 4 oc lanes x 8 c-pairs
            ull wp0[8], wp1[8], wp2[8], wp3[8];
            const float* wb = w_s + g * 1024 + ocg * 4;
#pragma unroll
            for (int c2 = 0; c2 < 8; c2++) {
                float4 u = *(const float4*)(wb + (2 * c2) * 64);
                float4 v = *(const float4*)(wb + (2 * c2 + 1) * 64);
                wp0[c2] = pack2(u.x, v.x);
                wp1[c2] = pack2(u.y, v.y);
                wp2[c2] = pack2(u.z, v.z);
                wp3[c2] = pack2(u.w, v.w);
            }
            const int cnt = cnt_s[g];
            for (int i = slot; i < cnt; i += 16) {
                int pk = list_s[g * NIN + i];
                int ly = pk >> 6, lx = pk & 63;
                int oy = ly - ky, ox = lx - kx;
                if ((unsigned)oy < (unsigned)TY && (unsigned)ox < (unsigned)TX) {
                    const ull* xp = (const ull*)(x_s + (ly * IN_W + lx) * 16);
                    ull xv = xp[0];
                    ull a0 = mul2(wp0[0], xv);
                    ull a1 = mul2(wp1[0], xv);
                    ull a2 = mul2(wp2[0], xv);
                    ull a3 = mul2(wp3[0], xv);
#pragma unroll
                    for (int c2 = 1; c2 < 8; c2++) {
                        xv = xp[c2];
                        a0 = fma2(wp0[c2], xv, a0);
                        a1 = fma2(wp1[c2], xv, a1);
                        a2 = fma2(wp2[c2], xv, a2);
                        a3 = fma2(wp3[c2], xv, a3);
                    }
                    float l0, h0, l1, h1, l2, h2, l3, h3;
                    unpack2(l0, h0, a0);
                    unpack2(l1, h1, a1);
                    unpack2(l2, h2, a2);
                    unpack2(l3, h3, a3);
                    float4* ap = (float4*)(acc_s + (oy * TX + ox) * ACC_STRIDE + ocg * 4);
                    float4 av = *ap;
                    av.x += l0 + h0;
                    av.y += l1 + h1;
                    av.z += l2 + h2;
                    av.w += l3 + h3;
                    *ap = av;
                }
            }
        }
        __syncthreads();
    }

    // ---- epilogue: maxout group selection, one thread per pixel ----
    {
        const float* ar = acc_s + t * ACC_STRIDE;
        float best = -3.4e38f;
        int bi = 0;
#pragma unroll
        for (int og = 0; og < 4; og++) {
            float m = -3.4e38f;
#pragma unroll
            for (int k = 0; k < 16; k += 4) {
                float4 v = *(const float4*)(ar + og * 16 + k);
                m = fmaxf(m, fmaxf(fmaxf(v.x, v.y), fmaxf(v.z, v.w)));
            }
            if (m > best) { best = m; bi = og; }  // first-max tie-break (jnp.argmax)
        }
        int pyl = t >> 5, pxl = t & 31;
        size_t opix = ((size_t)b * 256 + (oy0 + pyl)) * 256 + (ox0 + pxl);
        float4* op = (float4*)(out + opix * 16);
        const float4* sp = (const float4*)(ar + bi * 16);
        op[0] = sp[0];
        op[1] = sp[1];
        op[2] = sp[2];
        op[3] = sp[3];
        if (write_idx) out_idx[opix] = (float)bi;
    }
}

extern "C" void kernel_launch(void* const* d_in, const int* in_sizes, int n_in,
                              void* d_out, int out_size) {
    const float* x = (const float*)d_in[0];
    const int* gi = (const int*)d_in[1];
    const float* w = (const float*)d_in[2];
    const float* bias = (const float*)d_in[3];
    float* out = (float*)d_out;

    const int n_sel = in_sizes[0];            // B*H*W*16 (sel output size)
    const int n_pix = in_sizes[1];            // B*H*W
    const int B = n_pix / (256 * 256);
    const int write_idx = (out_size >= n_sel + n_pix) ? 1 : 0;

    reorder_w_kernel<<<(9 * 4 * 16 * 64 + 255) / 256, 256>>>(w);

    cudaFuncSetAttribute(ssconv_main, cudaFuncAttributeMaxDynamicSharedMemorySize,
                         SMEM_BYTES);
    dim3 grid(256 / TX, 256 / TY, B);
    ssconv_main<<<grid, NTHREADS, SMEM_BYTES>>>(x, gi, bias, out, out + n_sel,
                                                write_idx);
}

// round 4
// speedup vs baseline: 1.1707x; 1.1696x over previous
#include <cuda_runtime.h>

// SSConv2d: per-pixel input-group routed 3x3 conv (64 oc) + maxout group select.
// fp32 FFMA2 path (tensor cores rejected: argmax discontinuity needs fp32-exact
// scores). Block = 32x8 output tile. Input pixels bucketed by in-group g into
// full-interior (checkless, all taps valid) and edge lists. Per (tap,g) the
// per-thread weight slice (16c x 4oc) lives in registers as f32x2 pairs loaded
// directly from a pre-packed global layout; x streams from smem via LDS.128;
// acc in padded smem tile, exclusive per tap (barrier between taps).

#define TX 32
#define TY 8
#define NPIX (TX * TY)      // 256
#define IN_W 34
#define IN_H 10
#define NIN (IN_W * IN_H)   // 340
#define ACC_STRIDE 68       // 4*17 floats per pixel row: conflict-free epilogue
#define NTHREADS 256
#define FULL_CAP 184        // interior pixels: max 6*30 = 180
#define EDGE_CAP 164        // edge pixels: max 340-180 = 160

typedef unsigned long long ull;

// pre-packed weights: [tap(9)][g(4)][c2(8)][oc(64)][{c even, c odd}]
__device__ float g_wp[9 * 4 * 8 * 128];

__global__ void prepack_w(const float* __restrict__ w) {
    int i = blockIdx.x * blockDim.x + threadIdx.x;
    if (i >= 9 * 4 * 8 * 128) return;
    int h   = i & 1;
    int oc  = (i >> 1) & 63;
    int c2  = (i >> 7) & 7;
    int g   = (i >> 10) & 3;
    int tap = i >> 12;
    int c = c2 * 2 + h;
    // weight layout: [oc][ic = g*16 + c][ky][kx], tap = ky*3 + kx
    g_wp[i] = w[(oc * 64 + g * 16 + c) * 9 + tap];
}

__device__ __forceinline__ void unpack2(float& lo, float& hi, ull v) {
    asm("mov.b64 {%0, %1}, %2;" : "=f"(lo), "=f"(hi) : "l"(v));
}
__device__ __forceinline__ ull fma2(ull a, ull b, ull c) {
    ull d;
    asm("fma.rn.f32x2 %0, %1, %2, %3;" : "=l"(d) : "l"(a), "l"(b), "l"(c));
    return d;
}
__device__ __forceinline__ ull mul2(ull a, ull b) {
    ull d;
    asm("mul.rn.f32x2 %0, %1, %2;" : "=l"(d) : "l"(a), "l"(b));
    return d;
}

struct PixAcc {
    ull a0, a1, a2, a3;
    float* ap;
};

// compute partial dot (16c x 4oc) for one pixel; no commit yet (caller batches
// two of these for ILP before the smem RMWs)
__device__ __forceinline__ PixAcc pix_compute(
    unsigned e, int ky, int kx, const float* x_s, float* acc_s, int ocg,
    const ull (&wA)[8], const ull (&wB)[8], const ull (&wC)[8], const ull (&wD)[8])
{
    PixAcc r;
    int co = e & 0xffff;
    int oy = (co >> 6) - ky;
    int ox = (co & 63) - kx;
    r.ap = acc_s + (oy * TX + ox) * ACC_STRIDE + ocg * 4;
    const ulonglong2* xp = (const ulonglong2*)((const char*)x_s + (e >> 16));
    ulonglong2 p0 = xp[0];
    ulonglong2 p1 = xp[1];
    r.a0 = mul2(wA[0], p0.x);
    r.a1 = mul2(wB[0], p0.x);
    r.a2 = mul2(wC[0], p0.x);
    r.a3 = mul2(wD[0], p0.x);
    r.a0 = fma2(wA[1], p0.y, r.a0);
    r.a1 = fma2(wB[1], p0.y, r.a1);
    r.a2 = fma2(wC[1], p0.y, r.a2);
    r.a3 = fma2(wD[1], p0.y, r.a3);
    r.a0 = fma2(wA[2], p1.x, r.a0);
    r.a1 = fma2(wB[2], p1.x, r.a1);
    r.a2 = fma2(wC[2], p1.x, r.a2);
    r.a3 = fma2(wD[2], p1.x, r.a3);
    r.a0 = fma2(wA[3], p1.y, r.a0);
    r.a1 = fma2(wB[3], p1.y, r.a1);
    r.a2 = fma2(wC[3], p1.y, r.a2);
    r.a3 = fma2(wD[3], p1.y, r.a3);
    ulonglong2 p2 = xp[2];
    ulonglong2 p3 = xp[3];
    r.a0 = fma2(wA[4], p2.x, r.a0);
    r.a1 = fma2(wB[4], p2.x, r.a1);
    r.a2 = fma2(wC[4], p2.x, r.a2);
    r.a3 = fma2(wD[4], p2.x, r.a3);
    r.a0 = fma2(wA[5], p2.y, r.a0);
    r.a1 = fma2(wB[5], p2.y, r.a1);
    r.a2 = fma2(wC[5], p2.y, r.a2);
    r.a3 = fma2(wD[5], p2.y, r.a3);
    r.a0 = fma2(wA[6], p3.x, r.a0);
    r.a1 = fma2(wB[6], p3.x, r.a1);
    r.a2 = fma2(wC[6], p3.x, r.a2);
    r.a3 = fma2(wD[6], p3.x, r.a3);
    r.a0 = fma2(wA[7], p3.y, r.a0);
    r.a1 = fma2(wB[7], p3.y, r.a1);
    r.a2 = fma2(wC[7], p3.y, r.a2);
    r.a3 = fma2(wD[7], p3.y, r.a3);
    return r;
}

__device__ __forceinline__ void pix_commit(const PixAcc& r) {
    float4 av = *(float4*)r.ap;
    float l, h;
    unpack2(l, h, r.a0); av.x += l + h;
    unpack2(l, h, r.a1); av.y += l + h;
    unpack2(l, h, r.a2); av.z += l + h;
    unpack2(l, h, r.a3); av.w += l + h;
    *(float4*)r.ap = av;
}

// smem layout (bytes):
//   x_s   : NIN*16 floats             = 21760
//   acc_s : NPIX*ACC_STRIDE floats    = 69632
//   fl    : 4*FULL_CAP uints          = 2944
//   el    : 4*EDGE_CAP uints          = 2624
//   cnts  : 8 ints                    = 32
#define SMEM_BYTES ((NIN * 16 + NPIX * ACC_STRIDE) * 4 + 4 * FULL_CAP * 4 + \
                    4 * EDGE_CAP * 4 + 32)

extern __shared__ float smem_dyn[];

__global__ __launch_bounds__(NTHREADS, 2)
void ssconv_main(const float* __restrict__ x, const int* __restrict__ gidx,
                 const float* __restrict__ bias, float* __restrict__ out,
                 float* __restrict__ out_idx, int write_idx) {
    float* x_s = smem_dyn;
    float* acc_s = x_s + NIN * 16;
    unsigned* fl = (unsigned*)(acc_s + NPIX * ACC_STRIDE);
    unsigned* el = fl + 4 * FULL_CAP;
    int* cntf = (int*)(el + 4 * EDGE_CAP);
    int* cnte = cntf + 4;

    const int t = threadIdx.x;
    const int b = blockIdx.z;
    const int oy0 = blockIdx.y * TY;
    const int ox0 = blockIdx.x * TX;

    if (t < 8) cntf[t] = 0;
    __syncthreads();

    // ---- load input tile (with halo) into smem ----
    for (int f = t; f < NIN * 4; f += NTHREADS) {
        int p = f >> 2, c4 = f & 3;
        int ly = p / IN_W, lx = p - ly * IN_W;
        int iy = oy0 - 1 + ly, ix = ox0 - 1 + lx;
        float4 v = make_float4(0.f, 0.f, 0.f, 0.f);
        if ((unsigned)iy < 256u && (unsigned)ix < 256u)
            v = *(const float4*)(x + (((size_t)b * 256 + iy) * 256 + ix) * 16 + c4 * 4);
        *(float4*)(x_s + p * 16 + c4 * 4) = v;
    }
    // ---- classify input pixels into (g, full/edge) buckets ----
    for (int p = t; p < NIN; p += NTHREADS) {
        int ly = p / IN_W, lx = p - ly * IN_W;
        int iy = oy0 - 1 + ly, ix = ox0 - 1 + lx;
        if ((unsigned)iy < 256u && (unsigned)ix < 256u) {
            int g = gidx[((size_t)b * 256 + iy) * 256 + ix];
            unsigned e = ((unsigned)(p * 64) << 16) | (unsigned)((ly << 6) | lx);
            bool full = (ly >= 2) & (ly <= TY - 1) & (lx >= 2) & (lx <= TX - 1);
            if (full) fl[g * FULL_CAP + atomicAdd(&cntf[g], 1)] = e;
            else      el[g * EDGE_CAP + atomicAdd(&cnte[g], 1)] = e;
        }
    }
    // ---- init accumulators to bias ----
    for (int f = t; f < NPIX * 17; f += NTHREADS) {
        int c4 = f % 17;
        float4 v = make_float4(0.f, 0.f, 0.f, 0.f);
        if (c4 < 16) v = *(const float4*)(bias + c4 * 4);
        ((float4*)acc_s)[f] = v;
    }
    __syncthreads();

    const int ocg = t & 15;   // 16 groups of 4 consecutive out-channels
    const int slot = t >> 4;  // 16 parallel slots over the pixel lists

#pragma unroll 1
    for (int tap = 0; tap < 9; tap++) {
        const int ky = tap / 3;
        const int kx = tap - ky * 3;

#pragma unroll 1
        for (int g = 0; g < 4; g++) {
            // weights for (tap, g): 16 LDG.128 straight into registers
            ull wA[8], wB[8], wC[8], wD[8];
            const ulonglong2* wb =
                (const ulonglong2*)(g_wp + (tap * 4 + g) * 1024 + ocg * 8);
#pragma unroll
            for (int c2 = 0; c2 < 8; c2++) {
                ulonglong2 q0 = wb[c2 * 32];
                ulonglong2 q1 = wb[c2 * 32 + 1];
                wA[c2] = q0.x; wB[c2] = q0.y;
                wC[c2] = q1.x; wD[c2] = q1.y;
            }

            // full-interior list: no bounds check, 2 pixels per iteration
            {
                const unsigned* L = fl + g * FULL_CAP;
                const int n = cntf[g];
                int i = slot * 2;
                for (; i + 1 < n; i += 32) {
                    unsigned e0 = L[i], e1 = L[i + 1];
                    PixAcc A = pix_compute(e0, ky, kx, x_s, acc_s, ocg, wA, wB, wC, wD);
                    PixAcc B = pix_compute(e1, ky, kx, x_s, acc_s, ocg, wA, wB, wC, wD);
                    pix_commit(A);
                    pix_commit(B);
                }
                if (i < n) {
                    PixAcc A = pix_compute(L[i], ky, kx, x_s, acc_s, ocg, wA, wB, wC, wD);
                    pix_commit(A);
                }
            }
            // edge list: bounds-checked
            {
                const unsigned* L = el + g * EDGE_CAP;
                const int n = cnte[g];
                for (int i = slot; i < n; i += 16) {
                    unsigned e = L[i];
                    int co = e & 0xffff;
                    int oy = (co >> 6) - ky, ox = (co & 63) - kx;
                    if ((unsigned)oy < (unsigned)TY && (unsigned)ox < (unsigned)TX) {
                        PixAcc A = pix_compute(e, ky, kx, x_s, acc_s, ocg, wA, wB, wC, wD);
                        pix_commit(A);
                    }
                }
            }
        }
        __syncthreads();
    }

    // ---- epilogue: maxout group selection, one thread per pixel ----
    {
        const float* ar = acc_s + t * ACC_STRIDE;
        float best = -3.4e38f;
        int bi = 0;
#pragma unroll
        for (int og = 0; og < 4; og++) {
            float m = -3.4e38f;
#pragma unroll
            for (int k = 0; k < 16; k += 4) {
                float4 v = *(const float4*)(ar + og * 16 + k);
                m = fmaxf(m, fmaxf(fmaxf(v.x, v.y), fmaxf(v.z, v.w)));
            }
            if (m > best) { best = m; bi = og; }  // first-max tie-break (jnp.argmax)
        }
        int pyl = t >> 5, pxl = t & 31;
        size_t opix = ((size_t)b * 256 + (oy0 + pyl)) * 256 + (ox0 + pxl);
        float4* op = (float4*)(out + opix * 16);
        const float4* sp = (const float4*)(ar + bi * 16);
        op[0] = sp[0];
        op[1] = sp[1];
        op[2] = sp[2];
        op[3] = sp[3];
        if (write_idx) out_idx[opix] = (float)bi;
    }
}

extern "C" void kernel_launch(void* const* d_in, const int* in_sizes, int n_in,
                              void* d_out, int out_size) {
    const float* x = (const float*)d_in[0];
    const int* gi = (const int*)d_in[1];
    const float* w = (const float*)d_in[2];
    const float* bias = (const float*)d_in[3];
    float* out = (float*)d_out;

    const int n_sel = in_sizes[0];  // B*H*W*16 (sel output size)
    const int n_pix = in_sizes[1];  // B*H*W
    const int B = n_pix / (256 * 256);
    const int write_idx = (out_size >= n_sel + n_pix) ? 1 : 0;

    prepack_w<<<(9 * 4 * 8 * 128 + 255) / 256, 256>>>(w);

    cudaFuncSetAttribute(ssconv_main, cudaFuncAttributeMaxDynamicSharedMemorySize,
                         SMEM_BYTES);
    dim3 grid(256 / TX, 256 / TY, B);
    ssconv_main<<<grid, NTHREADS, SMEM_BYTES>>>(x, gi, bias, out, out + n_sel,
                                                write_idx);
}

// round 5
// speedup vs baseline: 1.4197x; 1.2127x over previous
#include <cuda_runtime.h>

// SSConv2d: per-pixel input-group routed 3x3 conv (64 oc) + maxout group select.
// fp32 FFMA2 path. Block = 32x8 output tile. Input pixels bucketed by in-group
// g into full-interior (checkless) and edge lists. Weights staged per-tap into
// smem in a conflict-free pre-packed layout, then per (tap,g) the per-thread
// slice (16c x 4oc) is pulled into registers via 16 LDS.128 (no pack movs).
// x streams from smem via broadcast LDS.128; acc in padded smem tile with
// per-tap exclusive ownership (barrier between taps => race free).

#define TX 32
#define TY 8
#define NPIX (TX * TY)      // 256
#define IN_W 34
#define IN_H 10
#define NIN (IN_W * IN_H)   // 340
#define ACC_STRIDE 68       // 4*17 floats per pixel: 4-way-max epilogue conflicts
#define NTHREADS 256
#define FULL_CAP 184        // interior pixels: max 6*30 = 180
#define EDGE_CAP 164        // edge pixels: max 340-180 = 160

typedef unsigned long long ull;

// pre-packed weights: [tap(9)][g(4)][c2(8)][q(2)][ocg(16)][4 floats]
// q=0 holds (ocA,ocB), q=1 holds (ocC,ocD); each 4-float unit = f32x2 pairs
// (c even, c odd) for two adjacent oc.
__device__ float g_wp[9 * 4 * 8 * 2 * 16 * 4];

__global__ void prepack_w(const float* __restrict__ w) {
    int i = blockIdx.x * blockDim.x + threadIdx.x;
    if (i >= 36864) return;
    int j   = i & 3;
    int ocg = (i >> 2) & 15;
    int q   = (i >> 6) & 1;
    int c2  = (i >> 7) & 7;
    int g   = (i >> 10) & 3;
    int tap = i >> 12;
    int oc = ocg * 4 + q * 2 + (j >> 1);
    int c  = c2 * 2 + (j & 1);
    // weight layout: [oc][ic = g*16 + c][ky][kx], tap = ky*3 + kx
    g_wp[i] = w[(oc * 64 + g * 16 + c) * 9 + tap];
}

__device__ __forceinline__ void unpack2(float& lo, float& hi, ull v) {
    asm("mov.b64 {%0, %1}, %2;" : "=f"(lo), "=f"(hi) : "l"(v));
}
__device__ __forceinline__ ull fma2(ull a, ull b, ull c) {
    ull d;
    asm("fma.rn.f32x2 %0, %1, %2, %3;" : "=l"(d) : "l"(a), "l"(b), "l"(c));
    return d;
}
__device__ __forceinline__ ull mul2(ull a, ull b) {
    ull d;
    asm("mul.rn.f32x2 %0, %1, %2;" : "=l"(d) : "l"(a), "l"(b));
    return d;
}

struct PixAcc {
    ull a0, a1, a2, a3;
    float* ap;
};

// partial dot (16c x 4oc) for one pixel; commit deferred for ILP batching
__device__ __forceinline__ PixAcc pix_compute(
    int xpix, int accoff, const float* x_s, float* acc_s, int ocg,
    const ull (&wA)[8], const ull (&wB)[8], const ull (&wC)[8], const ull (&wD)[8])
{
    PixAcc r;
    r.ap = acc_s + accoff * ACC_STRIDE + ocg * 4;
    const ulonglong2* xp = (const ulonglong2*)(x_s + xpix * 16);
    ulonglong2 p0 = xp[0];
    ulonglong2 p1 = xp[1];
    r.a0 = mul2(wA[0], p0.x);
    r.a1 = mul2(wB[0], p0.x);
    r.a2 = mul2(wC[0], p0.x);
    r.a3 = mul2(wD[0], p0.x);
    r.a0 = fma2(wA[1], p0.y, r.a0);
    r.a1 = fma2(wB[1], p0.y, r.a1);
    r.a2 = fma2(wC[1], p0.y, r.a2);
    r.a3 = fma2(wD[1], p0.y, r.a3);
    r.a0 = fma2(wA[2], p1.x, r.a0);
    r.a1 = fma2(wB[2], p1.x, r.a1);
    r.a2 = fma2(wC[2], p1.x, r.a2);
    r.a3 = fma2(wD[2], p1.x, r.a3);
    r.a0 = fma2(wA[3], p1.y, r.a0);
    r.a1 = fma2(wB[3], p1.y, r.a1);
    r.a2 = fma2(wC[3], p1.y, r.a2);
    r.a3 = fma2(wD[3], p1.y, r.a3);
    ulonglong2 p2 = xp[2];
    ulonglong2 p3 = xp[3];
    r.a0 = fma2(wA[4], p2.x, r.a0);
    r.a1 = fma2(wB[4], p2.x, r.a1);
    r.a2 = fma2(wC[4], p2.x, r.a2);
    r.a3 = fma2(wD[4], p2.x, r.a3);
    r.a0 = fma2(wA[5], p2.y, r.a0);
    r.a1 = fma2(wB[5], p2.y, r.a1);
    r.a2 = fma2(wC[5], p2.y, r.a2);
    r.a3 = fma2(wD[5], p2.y, r.a3);
    r.a0 = fma2(wA[6], p3.x, r.a0);
    r.a1 = fma2(wB[6], p3.x, r.a1);
    r.a2 = fma2(wC[6], p3.x, r.a2);
    r.a3 = fma2(wD[6], p3.x, r.a3);
    r.a0 = fma2(wA[7], p3.y, r.a0);
    r.a1 = fma2(wB[7], p3.y, r.a1);
    r.a2 = fma2(wC[7], p3.y, r.a2);
    r.a3 = fma2(wD[7], p3.y, r.a3);
    return r;
}

__device__ __forceinline__ void pix_commit(const PixAcc& r) {
    float4 av = *(float4*)r.ap;
    float l, h;
    unpack2(l, h, r.a0); av.x += l + h;
    unpack2(l, h, r.a1); av.y += l + h;
    unpack2(l, h, r.a2); av.z += l + h;
    unpack2(l, h, r.a3); av.w += l + h;
    *(float4*)r.ap = av;
}

// smem layout (floats):
//   x_s   : NIN*16   = 5440
//   acc_s : 256*68   = 17408
//   w_s   : 4096     (one tap, all 4 g, packed)
//   then lists: fl 4*FULL_CAP uints, el 4*EDGE_CAP uints, 8 counters
#define SMEM_BYTES ((NIN * 16 + NPIX * ACC_STRIDE + 4096) * 4 + \
                    4 * FULL_CAP * 4 + 4 * EDGE_CAP * 4 + 32)

extern __shared__ float smem_dyn[];

__global__ __launch_bounds__(NTHREADS, 2)
void ssconv_main(const float* __restrict__ x, const int* __restrict__ gidx,
                 const float* __restrict__ bias, float* __restrict__ out,
                 float* __restrict__ out_idx, int write_idx) {
    float* x_s = smem_dyn;
    float* acc_s = x_s + NIN * 16;
    float* w_s = acc_s + NPIX * ACC_STRIDE;
    unsigned* fl = (unsigned*)(w_s + 4096);
    unsigned* el = fl + 4 * FULL_CAP;
    int* cntf = (int*)(el + 4 * EDGE_CAP);
    int* cnte = cntf + 4;

    const int t = threadIdx.x;
    const int b = blockIdx.z;
    const int oy0 = blockIdx.y * TY;
    const int ox0 = blockIdx.x * TX;

    if (t < 8) cntf[t] = 0;
    __syncthreads();

    // ---- load input tile (with halo) into smem ----
    for (int f = t; f < NIN * 4; f += NTHREADS) {
        int p = f >> 2, c4 = f & 3;
        int ly = p / IN_W, lx = p - ly * IN_W;
        int iy = oy0 - 1 + ly, ix = ox0 - 1 + lx;
        float4 v = make_float4(0.f, 0.f, 0.f, 0.f);
        if ((unsigned)iy < 256u && (unsigned)ix < 256u)
            v = *(const float4*)(x + (((size_t)b * 256 + iy) * 256 + ix) * 16 + c4 * 4);
        *(float4*)(x_s + p * 16 + c4 * 4) = v;
    }
    // ---- classify input pixels into (g, full/edge) buckets ----
    for (int p = t; p < NIN; p += NTHREADS) {
        int ly = p / IN_W, lx = p - ly * IN_W;
        int iy = oy0 - 1 + ly, ix = ox0 - 1 + lx;
        if ((unsigned)iy < 256u && (unsigned)ix < 256u) {
            int g = gidx[((size_t)b * 256 + iy) * 256 + ix];
            bool full = (ly >= 2) & (ly <= TY - 1) & (lx >= 2) & (lx <= TX - 1);
            if (full) {
                // interior: acc index arithmetic entry (pixpos valid: lx<=31)
                unsigned e = ((unsigned)p << 10) | (unsigned)(ly * TX + lx);
                fl[g * FULL_CAP + atomicAdd(&cntf[g], 1)] = e;
            } else {
                unsigned e = ((unsigned)p << 11) | (unsigned)((ly << 6) | lx);
                el[g * EDGE_CAP + atomicAdd(&cnte[g], 1)] = e;
            }
        }
    }
    // ---- init accumulators to bias ----
    for (int f = t; f < NPIX * 17; f += NTHREADS) {
        int c4 = f % 17;
        float4 v = make_float4(0.f, 0.f, 0.f, 0.f);
        if (c4 < 16) v = *(const float4*)(bias + c4 * 4);
        ((float4*)acc_s)[f] = v;
    }

    const int ocg = t & 15;   // 16 groups of 4 consecutive out-channels
    const int slot = t >> 4;  // 16 parallel slots over the pixel lists

#pragma unroll 1
    for (int tap = 0; tap < 9; tap++) {
        const int ky = tap / 3;
        const int kx = tap - ky * 3;
        const int tapoff = ky * TX + kx;

        // stage this tap's pre-packed weights (16KB) into smem
        __syncthreads();  // previous tap's w_s reads (and acc commits) complete
        {
            const float4* src = (const float4*)(g_wp + tap * 4096);
            float4* dst = (float4*)w_s;
#pragma unroll
            for (int k = 0; k < 4; k++)
                dst[t + k * NTHREADS] = src[t + k * NTHREADS];
        }
        __syncthreads();

#pragma unroll 1
        for (int g = 0; g < 4; g++) {
            // per-thread weight slice: 16 LDS.128, lanes read consecutive 16B
            ull wA[8], wB[8], wC[8], wD[8];
            const ulonglong2* wq = (const ulonglong2*)(w_s + g * 1024) + ocg;
#pragma unroll
            for (int c2 = 0; c2 < 8; c2++) {
                ulonglong2 q0 = wq[c2 * 32];       // [c2][q=0][ocg]
                ulonglong2 q1 = wq[c2 * 32 + 16];  // [c2][q=1][ocg]
                wA[c2] = q0.x; wB[c2] = q0.y;
                wC[c2] = q1.x; wD[c2] = q1.y;
            }

            // full-interior list: no bounds check, 2 pixels per iteration
            {
                const unsigned* L = fl + g * FULL_CAP;
                const int n = cntf[g];
                int i = slot * 2;
                for (; i + 1 < n; i += 32) {
                    unsigned e0 = L[i], e1 = L[i + 1];
                    PixAcc A = pix_compute((int)(e0 >> 10), (int)(e0 & 1023) - tapoff,
                                           x_s, acc_s, ocg, wA, wB, wC, wD);
                    PixAcc B = pix_compute((int)(e1 >> 10), (int)(e1 & 1023) - tapoff,
                                           x_s, acc_s, ocg, wA, wB, wC, wD);
                    pix_commit(A);
                    pix_commit(B);
                }
                if (i < n) {
                    unsigned e0 = L[i];
                    PixAcc A = pix_compute((int)(e0 >> 10), (int)(e0 & 1023) - tapoff,
                                           x_s, acc_s, ocg, wA, wB, wC, wD);
                    pix_commit(A);
                }
            }
            // edge list: bounds-checked per tap
            {
                const unsigned* L = el + g * EDGE_CAP;
                const int n = cnte[g];
                for (int i = slot; i < n; i += 16) {
                    unsigned e = L[i];
                    int ly = (e >> 6) & 31, lx = e & 63;
                    int oy = ly - ky, ox = lx - kx;
                    if ((unsigned)oy < (unsigned)TY && (unsigned)ox < (unsigned)TX) {
                        PixAcc A = pix_compute((int)(e >> 11), oy * TX + ox,
                                               x_s, acc_s, ocg, wA, wB, wC, wD);
                        pix_commit(A);
                    }
                }
            }
        }
    }
    __syncthreads();

    // ---- epilogue: maxout group selection, one thread per pixel ----
    {
        const float* ar = acc_s + t * ACC_STRIDE;
        float best = -3.4e38f;
        int bi = 0;
#pragma unroll
        for (int og = 0; og < 4; og++) {
            float m = -3.4e38f;
#pragma unroll
            for (int k = 0; k < 16; k += 4) {
                float4 v = *(const float4*)(ar + og * 16 + k);
                m = fmaxf(m, fmaxf(fmaxf(v.x, v.y), fmaxf(v.z, v.w)));
            }
            if (m > best) { best = m; bi = og; }  // first-max tie-break (jnp.argmax)
        }
        int pyl = t >> 5, pxl = t & 31;
        size_t opix = ((size_t)b * 256 + (oy0 + pyl)) * 256 + (ox0 + pxl);
        float4* op = (float4*)(out + opix * 16);
        const float4* sp = (const float4*)(ar + bi * 16);
        op[0] = sp[0];
        op[1] = sp[1];
        op[2] = sp[2];
        op[3] = sp[3];
        if (write_idx) out_idx[opix] = (float)bi;
    }
}

extern "C" void kernel_launch(void* const* d_in, const int* in_sizes, int n_in,
                              void* d_out, int out_size) {
    const float* x = (const float*)d_in[0];
    const int* gi = (const int*)d_in[1];
    const float* w = (const float*)d_in[2];
    const float* bias = (const float*)d_in[3];
    float* out = (float*)d_out;

    const int n_sel = in_sizes[0];  // B*H*W*16 (sel output size)
    const int n_pix = in_sizes[1];  // B*H*W
    const int B = n_pix / (256 * 256);
    const int write_idx = (out_size >= n_sel + n_pix) ? 1 : 0;

    prepack_w<<<(36864 + 255) / 256, 256>>>(w);

    cudaFuncSetAttribute(ssconv_main, cudaFuncAttributeMaxDynamicSharedMemorySize,
                         SMEM_BYTES);
    dim3 grid(256 / TX, 256 / TY, B);
    ssconv_main<<<grid, NTHREADS, SMEM_BYTES>>>(x, gi, bias, out, out + n_sel,
                                                write_idx);
}

// round 6
// speedup vs baseline: 1.7452x; 1.2293x over previous
#include <cuda_runtime.h>

// SSConv2d: per-pixel input-group routed 3x3 conv (64 oc) + maxout group select.
// fp32 FFMA2 path. Block = 32x8 output tile. Input pixels bucketed by in-group
// g into full-interior (checkless) and edge lists. Groups partitioned across
// warp-pairs: warps {2g, 2g+1} own group g, so each warp loads only its own
// (tap,g) weight slice (16 LDG.128/tap, L1-resident prepacked layout) and keeps
// it in registers across its whole pixel list. x streams from smem via
// broadcast LDS.128; acc in padded smem tile, exclusive per tap (barrier
// between taps => race free, deterministic tap-order accumulation).

#define TX 32
#define TY 8
#define NPIX (TX * TY)      // 256
#define IN_W 34
#define IN_H 10
#define NIN (IN_W * IN_H)   // 340
#define ACC_STRIDE 68       // 4*17 floats per pixel row
#define NTHREADS 256
#define FULL_CAP 184        // interior pixels: max 6*30 = 180
#define EDGE_CAP 164        // edge pixels: max 340-180 = 160

typedef unsigned long long ull;

// pre-packed weights: [tap(9)][g(4)][c2(8)][q(2)][ocg(16)][4 floats]
// q=0 holds (ocA,ocB), q=1 holds (ocC,ocD); each 4-float unit = f32x2 pairs
// (c even, c odd) for two adjacent oc.
__device__ float g_wp[9 * 4 * 8 * 2 * 16 * 4];

__global__ void prepack_w(const float* __restrict__ w) {
    int i = blockIdx.x * blockDim.x + threadIdx.x;
    if (i >= 36864) return;
    int j   = i & 3;
    int ocg = (i >> 2) & 15;
    int q   = (i >> 6) & 1;
    int c2  = (i >> 7) & 7;
    int g   = (i >> 10) & 3;
    int tap = i >> 12;
    int oc = ocg * 4 + q * 2 + (j >> 1);
    int c  = c2 * 2 + (j & 1);
    // weight layout: [oc][ic = g*16 + c][ky][kx], tap = ky*3 + kx
    g_wp[i] = w[(oc * 64 + g * 16 + c) * 9 + tap];
}

__device__ __forceinline__ void unpack2(float& lo, float& hi, ull v) {
    asm("mov.b64 {%0, %1}, %2;" : "=f"(lo), "=f"(hi) : "l"(v));
}
__device__ __forceinline__ ull fma2(ull a, ull b, ull c) {
    ull d;
    asm("fma.rn.f32x2 %0, %1, %2, %3;" : "=l"(d) : "l"(a), "l"(b), "l"(c));
    return d;
}
__device__ __forceinline__ ull mul2(ull a, ull b) {
    ull d;
    asm("mul.rn.f32x2 %0, %1, %2;" : "=l"(d) : "l"(a), "l"(b));
    return d;
}

struct PixAcc {
    ull a0, a1, a2, a3;
    float* ap;
};

// partial dot (16c x 4oc) for one pixel; commit deferred for ILP batching
__device__ __forceinline__ PixAcc pix_compute(
    int xpix, int accoff, const float* x_s, float* acc_s, int ocg,
    const ull (&wA)[8], const ull (&wB)[8], const ull (&wC)[8], const ull (&wD)[8])
{
    PixAcc r;
    r.ap = acc_s + accoff * ACC_STRIDE + ocg * 4;
    const ulonglong2* xp = (const ulonglong2*)(x_s + xpix * 16);
    ulonglong2 p0 = xp[0];
    ulonglong2 p1 = xp[1];
    r.a0 = mul2(wA[0], p0.x);
    r.a1 = mul2(wB[0], p0.x);
    r.a2 = mul2(wC[0], p0.x);
    r.a3 = mul2(wD[0], p0.x);
    r.a0 = fma2(wA[1], p0.y, r.a0);
    r.a1 = fma2(wB[1], p0.y, r.a1);
    r.a2 = fma2(wC[1], p0.y, r.a2);
    r.a3 = fma2(wD[1], p0.y, r.a3);
    r.a0 = fma2(wA[2], p1.x, r.a0);
    r.a1 = fma2(wB[2], p1.x, r.a1);
    r.a2 = fma2(wC[2], p1.x, r.a2);
    r.a3 = fma2(wD[2], p1.x, r.a3);
    r.a0 = fma2(wA[3], p1.y, r.a0);
    r.a1 = fma2(wB[3], p1.y, r.a1);
    r.a2 = fma2(wC[3], p1.y, r.a2);
    r.a3 = fma2(wD[3], p1.y, r.a3);
    ulonglong2 p2 = xp[2];
    ulonglong2 p3 = xp[3];
    r.a0 = fma2(wA[4], p2.x, r.a0);
    r.a1 = fma2(wB[4], p2.x, r.a1);
    r.a2 = fma2(wC[4], p2.x, r.a2);
    r.a3 = fma2(wD[4], p2.x, r.a3);
    r.a0 = fma2(wA[5], p2.y, r.a0);
    r.a1 = fma2(wB[5], p2.y, r.a1);
    r.a2 = fma2(wC[5], p2.y, r.a2);
    r.a3 = fma2(wD[5], p2.y, r.a3);
    r.a0 = fma2(wA[6], p3.x, r.a0);
    r.a1 = fma2(wB[6], p3.x, r.a1);
    r.a2 = fma2(wC[6], p3.x, r.a2);
    r.a3 = fma2(wD[6], p3.x, r.a3);
    r.a0 = fma2(wA[7], p3.y, r.a0);
    r.a1 = fma2(wB[7], p3.y, r.a1);
    r.a2 = fma2(wC[7], p3.y, r.a2);
    r.a3 = fma2(wD[7], p3.y, r.a3);
    return r;
}

__device__ __forceinline__ void pix_commit(const PixAcc& r) {
    float4 av = *(float4*)r.ap;
    float l, h;
    unpack2(l, h, r.a0); av.x += l + h;
    unpack2(l, h, r.a1); av.y += l + h;
    unpack2(l, h, r.a2); av.z += l + h;
    unpack2(l, h, r.a3); av.w += l + h;
    *(float4*)r.ap = av;
}

// smem layout (floats): x_s NIN*16 = 5440, acc_s 256*68 = 17408,
// then lists: fl 4*FULL_CAP uints, el 4*EDGE_CAP uints, 8 counters
#define SMEM_BYTES ((NIN * 16 + NPIX * ACC_STRIDE) * 4 + \
                    4 * FULL_CAP * 4 + 4 * EDGE_CAP * 4 + 32)

extern __shared__ float smem_dyn[];

__global__ __launch_bounds__(NTHREADS, 2)
void ssconv_main(const float* __restrict__ x, const int* __restrict__ gidx,
                 const float* __restrict__ bias, float* __restrict__ out,
                 float* __restrict__ out_idx, int write_idx) {
    float* x_s = smem_dyn;
    float* acc_s = x_s + NIN * 16;
    unsigned* fl = (unsigned*)(acc_s + NPIX * ACC_STRIDE);
    unsigned* el = fl + 4 * FULL_CAP;
    int* cntf = (int*)(el + 4 * EDGE_CAP);
    int* cnte = cntf + 4;

    const int t = threadIdx.x;
    const int b = blockIdx.z;
    const int oy0 = blockIdx.y * TY;
    const int ox0 = blockIdx.x * TX;

    if (t < 8) cntf[t] = 0;
    __syncthreads();

    // ---- load input tile (with halo) into smem ----
    for (int f = t; f < NIN * 4; f += NTHREADS) {
        int p = f >> 2, c4 = f & 3;
        int ly = p / IN_W, lx = p - ly * IN_W;
        int iy = oy0 - 1 + ly, ix = ox0 - 1 + lx;
        float4 v = make_float4(0.f, 0.f, 0.f, 0.f);
        if ((unsigned)iy < 256u && (unsigned)ix < 256u)
            v = *(const float4*)(x + (((size_t)b * 256 + iy) * 256 + ix) * 16 + c4 * 4);
        *(float4*)(x_s + p * 16 + c4 * 4) = v;
    }
    // ---- classify input pixels into (g, full/edge) buckets ----
    for (int p = t; p < NIN; p += NTHREADS) {
        int ly = p / IN_W, lx = p - ly * IN_W;
        int iy = oy0 - 1 + ly, ix = ox0 - 1 + lx;
        if ((unsigned)iy < 256u && (unsigned)ix < 256u) {
            int g = gidx[((size_t)b * 256 + iy) * 256 + ix];
            bool full = (ly >= 2) & (ly <= TY - 1) & (lx >= 2) & (lx <= TX - 1);
            if (full) {
                unsigned e = ((unsigned)p << 10) | (unsigned)(ly * TX + lx);
                fl[g * FULL_CAP + atomicAdd(&cntf[g], 1)] = e;
            } else {
                unsigned e = ((unsigned)p << 11) | (unsigned)((ly << 6) | lx);
                el[g * EDGE_CAP + atomicAdd(&cnte[g], 1)] = e;
            }
        }
    }
    // ---- init accumulators to bias ----
    for (int f = t; f < NPIX * 17; f += NTHREADS) {
        int c4 = f % 17;
        float4 v = make_float4(0.f, 0.f, 0.f, 0.f);
        if (c4 < 16) v = *(const float4*)(bias + c4 * 4);
        ((float4*)acc_s)[f] = v;
    }
    __syncthreads();

    const int g   = t >> 6;        // warp pair {2g, 2g+1} owns group g
    const int ocg = t & 15;        // 16 groups of 4 consecutive out-channels
    const int sid = (t >> 4) & 3;  // 4 slots over this g's pixel lists
    const int nf = cntf[g];
    const int ne = cnte[g];
    const unsigned* Lf = fl + g * FULL_CAP;
    const unsigned* Le = el + g * EDGE_CAP;

#pragma unroll 1
    for (int tap = 0; tap < 9; tap++) {
        const int ky = tap / 3;
        const int kx = tap - ky * 3;
        const int tapoff = ky * TX + kx;

        // this warp's (tap, g) weight slice: 16 LDG.128 (L1-resident hot set)
        ull wA[8], wB[8], wC[8], wD[8];
        const ulonglong2* wq =
            (const ulonglong2*)(g_wp + (tap * 4 + g) * 1024) + ocg;
#pragma unroll
        for (int c2 = 0; c2 < 8; c2++) {
            ulonglong2 q0 = wq[c2 * 32];       // [c2][q=0][ocg]
            ulonglong2 q1 = wq[c2 * 32 + 16];  // [c2][q=1][ocg]
            wA[c2] = q0.x; wB[c2] = q0.y;
            wC[c2] = q1.x; wD[c2] = q1.y;
        }

        // full-interior list: no bounds check, 2 pixels per iteration
        {
            int i = sid * 2;
            for (; i + 1 < nf; i += 8) {
                unsigned e0 = Lf[i], e1 = Lf[i + 1];
                PixAcc A = pix_compute((int)(e0 >> 10), (int)(e0 & 1023) - tapoff,
                                       x_s, acc_s, ocg, wA, wB, wC, wD);
                PixAcc B = pix_compute((int)(e1 >> 10), (int)(e1 & 1023) - tapoff,
                                       x_s, acc_s, ocg, wA, wB, wC, wD);
                pix_commit(A);
                pix_commit(B);
            }
            if (i < nf) {
                unsigned e0 = Lf[i];
                PixAcc A = pix_compute((int)(e0 >> 10), (int)(e0 & 1023) - tapoff,
                                       x_s, acc_s, ocg, wA, wB, wC, wD);
                pix_commit(A);
            }
        }
        // edge list: bounds-checked per tap
        for (int i = sid; i < ne; i += 4) {
            unsigned e = Le[i];
            int ly = (e >> 6) & 31, lx = e & 63;
            int oy = ly - ky, ox = lx - kx;
            if ((unsigned)oy < (unsigned)TY && (unsigned)ox < (unsigned)TX) {
                PixAcc A = pix_compute((int)(e >> 11), oy * TX + ox,
                                       x_s, acc_s, ocg, wA, wB, wC, wD);
                pix_commit(A);
            }
        }
        __syncthreads();  // acc ownership handoff between taps
    }

    // ---- epilogue: maxout group selection, one thread per pixel ----
    {
        const float* ar = acc_s + t * ACC_STRIDE;
        float best = -3.4e38f;
        int bi = 0;
#pragma unroll
        for (int og = 0; og < 4; og++) {
            float m = -3.4e38f;
#pragma unroll
            for (int k = 0; k < 16; k += 4) {
                float4 v = *(const float4*)(ar + og * 16 + k);
                m = fmaxf(m, fmaxf(fmaxf(v.x, v.y), fmaxf(v.z, v.w)));
            }
            if (m > best) { best = m; bi = og; }  // first-max tie-break (jnp.argmax)
        }
        int pyl = t >> 5, pxl = t & 31;
        size_t opix = ((size_t)b * 256 + (oy0 + pyl)) * 256 + (ox0 + pxl);
        float4* op = (float4*)(out + opix * 16);
        const float4* sp = (const float4*)(ar + bi * 16);
        op[0] = sp[0];
        op[1] = sp[1];
        op[2] = sp[2];
        op[3] = sp[3];
        if (write_idx) out_idx[opix] = (float)bi;
    }
}

extern "C" void kernel_launch(void* const* d_in, const int* in_sizes, int n_in,
                              void* d_out, int out_size) {
    const float* x = (const float*)d_in[0];
    const int* gi = (const int*)d_in[1];
    const float* w = (const float*)d_in[2];
    const float* bias = (const float*)d_in[3];
    float* out = (float*)d_out;

    const int n_sel = in_sizes[0];  // B*H*W*16 (sel output size)
    const int n_pix = in_sizes[1];  // B*H*W
    const int B = n_pix / (256 * 256);
    const int write_idx = (out_size >= n_sel + n_pix) ? 1 : 0;

    prepack_w<<<(36864 + 255) / 256, 256>>>(w);

    cudaFuncSetAttribute(ssconv_main, cudaFuncAttributeMaxDynamicSharedMemorySize,
                         SMEM_BYTES);
    dim3 grid(256 / TX, 256 / TY, B);
    ssconv_main<<<grid, NTHREADS, SMEM_BYTES>>>(x, gi, bias, out, out + n_sel,
                                                write_idx);
}

// round 7
// speedup vs baseline: 1.7521x; 1.0039x over previous
#include <cuda_runtime.h>

// SSConv2d: per-pixel input-group routed 3x3 conv (64 oc) + maxout group select.
// fp32 FFMA2 path. Block = 32x8 output tile. Input pixels bucketed by in-group
// g into full-interior (checkless) and edge lists. The 16 half-warp slots are
// allocated to groups PROPORTIONALLY to per-g work (2*interior+edge, largest-
// remainder rounding, >=1 slot per nonempty g) so per-tap barriers don't wait
// on the unlucky-largest group. Each slot keeps its (tap,g) weight slice
// (16c x 4oc) in registers via 16 LDG.128 from an L1-resident prepacked
// layout; x streams from smem via LDS.128; acc in padded smem tile with
// per-tap exclusive ownership (barrier between taps => race free).

#define TX 32
#define TY 8
#define NPIX (TX * TY)      // 256
#define IN_W 34
#define IN_H 10
#define NIN (IN_W * IN_H)   // 340
#define ACC_STRIDE 68       // 68 floats = 272 B per pixel row
#define NTHREADS 256
#define FULL_CAP 184        // interior pixels: max 6*30 = 180
#define EDGE_CAP 164        // edge pixels: max 340-180 = 160

typedef unsigned long long ull;

// pre-packed weights: [tap(9)][g(4)][c2(8)][q(2)][ocg(16)][4 floats]
__device__ float g_wp[9 * 4 * 8 * 2 * 16 * 4];

__global__ void prepack_w(const float* __restrict__ w) {
    int i = blockIdx.x * blockDim.x + threadIdx.x;
    if (i >= 36864) return;
    int j   = i & 3;
    int ocg = (i >> 2) & 15;
    int q   = (i >> 6) & 1;
    int c2  = (i >> 7) & 7;
    int g   = (i >> 10) & 3;
    int tap = i >> 12;
    int oc = ocg * 4 + q * 2 + (j >> 1);
    int c  = c2 * 2 + (j & 1);
    g_wp[i] = w[(oc * 64 + g * 16 + c) * 9 + tap];
}

__device__ __forceinline__ void unpack2(float& lo, float& hi, ull v) {
    asm("mov.b64 {%0, %1}, %2;" : "=f"(lo), "=f"(hi) : "l"(v));
}
__device__ __forceinline__ ull fma2(ull a, ull b, ull c) {
    ull d;
    asm("fma.rn.f32x2 %0, %1, %2, %3;" : "=l"(d) : "l"(a), "l"(b), "l"(c));
    return d;
}
__device__ __forceinline__ ull mul2(ull a, ull b) {
    ull d;
    asm("mul.rn.f32x2 %0, %1, %2;" : "=l"(d) : "l"(a), "l"(b));
    return d;
}

struct PixAcc {
    ull a0, a1, a2, a3;
    float* ap;
};

// partial dot (16c x 4oc) for one pixel, byte-offset addressed
__device__ __forceinline__ PixAcc pix_compute(
    int xoffB, int accoffB, const char* xb, char* accb,
    const ull (&wA)[8], const ull (&wB)[8], const ull (&wC)[8], const ull (&wD)[8])
{
    PixAcc r;
    r.ap = (float*)(accb + accoffB);
    const ulonglong2* xp = (const ulonglong2*)(xb + xoffB);
    ulonglong2 p0 = xp[0];
    ulonglong2 p1 = xp[1];
    r.a0 = mul2(wA[0], p0.x);
    r.a1 = mul2(wB[0], p0.x);
    r.a2 = mul2(wC[0], p0.x);
    r.a3 = mul2(wD[0], p0.x);
    r.a0 = fma2(wA[1], p0.y, r.a0);
    r.a1 = fma2(wB[1], p0.y, r.a1);
    r.a2 = fma2(wC[1], p0.y, r.a2);
    r.a3 = fma2(wD[1], p0.y, r.a3);
    r.a0 = fma2(wA[2], p1.x, r.a0);
    r.a1 = fma2(wB[2], p1.x, r.a1);
    r.a2 = fma2(wC[2], p1.x, r.a2);
    r.a3 = fma2(wD[2], p1.x, r.a3);
    r.a0 = fma2(wA[3], p1.y, r.a0);
    r.a1 = fma2(wB[3], p1.y, r.a1);
    r.a2 = fma2(wC[3], p1.y, r.a2);
    r.a3 = fma2(wD[3], p1.y, r.a3);
    ulonglong2 p2 = xp[2];
    ulonglong2 p3 = xp[3];
    r.a0 = fma2(wA[4], p2.x, r.a0);
    r.a1 = fma2(wB[4], p2.x, r.a1);
    r.a2 = fma2(wC[4], p2.x, r.a2);
    r.a3 = fma2(wD[4], p2.x, r.a3);
    r.a0 = fma2(wA[5], p2.y, r.a0);
    r.a1 = fma2(wB[5], p2.y, r.a1);
    r.a2 = fma2(wC[5], p2.y, r.a2);
    r.a3 = fma2(wD[5], p2.y, r.a3);
    r.a0 = fma2(wA[6], p3.x, r.a0);
    r.a1 = fma2(wB[6], p3.x, r.a1);
    r.a2 = fma2(wC[6], p3.x, r.a2);
    r.a3 = fma2(wD[6], p3.x, r.a3);
    r.a0 = fma2(wA[7], p3.y, r.a0);
    r.a1 = fma2(wB[7], p3.y, r.a1);
    r.a2 = fma2(wC[7], p3.y, r.a2);
    r.a3 = fma2(wD[7], p3.y, r.a3);
    return r;
}

__device__ __forceinline__ void pix_commit(const PixAcc& r) {
    float4 av = *(float4*)r.ap;
    float l, h;
    unpack2(l, h, r.a0); av.x += l + h;
    unpack2(l, h, r.a1); av.y += l + h;
    unpack2(l, h, r.a2); av.z += l + h;
    unpack2(l, h, r.a3); av.w += l + h;
    *(float4*)r.ap = av;
}

#define SMEM_BYTES ((NIN * 16 + NPIX * ACC_STRIDE) * 4 + \
                    4 * FULL_CAP * 4 + 4 * EDGE_CAP * 4 + 32)

extern __shared__ float smem_dyn[];

__global__ __launch_bounds__(NTHREADS, 2)
void ssconv_main(const float* __restrict__ x, const int* __restrict__ gidx,
                 const float* __restrict__ bias, float* __restrict__ out,
                 float* __restrict__ out_idx, int write_idx) {
    float* x_s = smem_dyn;
    float* acc_s = x_s + NIN * 16;
    unsigned* fl = (unsigned*)(acc_s + NPIX * ACC_STRIDE);
    unsigned* el = fl + 4 * FULL_CAP;
    int* cntf = (int*)(el + 4 * EDGE_CAP);
    int* cnte = cntf + 4;

    const int t = threadIdx.x;
    const int b = blockIdx.z;
    const int oy0 = blockIdx.y * TY;
    const int ox0 = blockIdx.x * TX;

    if (t < 8) cntf[t] = 0;
    __syncthreads();

    // ---- load input tile (with halo) into smem ----
    for (int f = t; f < NIN * 4; f += NTHREADS) {
        int p = f >> 2, c4 = f & 3;
        int ly = p / IN_W, lx = p - ly * IN_W;
        int iy = oy0 - 1 + ly, ix = ox0 - 1 + lx;
        float4 v = make_float4(0.f, 0.f, 0.f, 0.f);
        if ((unsigned)iy < 256u && (unsigned)ix < 256u)
            v = *(const float4*)(x + (((size_t)b * 256 + iy) * 256 + ix) * 16 + c4 * 4);
        *(float4*)(x_s + p * 16 + c4 * 4) = v;
    }
    // ---- classify input pixels into (g, full/edge) buckets ----
    for (int p = t; p < NIN; p += NTHREADS) {
        int ly = p / IN_W, lx = p - ly * IN_W;
        int iy = oy0 - 1 + ly, ix = ox0 - 1 + lx;
        if ((unsigned)iy < 256u && (unsigned)ix < 256u) {
            int g = gidx[((size_t)b * 256 + iy) * 256 + ix];
            bool full = (ly >= 2) & (ly <= TY - 1) & (lx >= 2) & (lx <= TX - 1);
            if (full) {
                // interior entry: (x byte offset << 17) | (acc byte offset)
                unsigned e = ((unsigned)p << 23) |
                             (unsigned)((ly * TX + lx) * (ACC_STRIDE * 4));
                fl[g * FULL_CAP + atomicAdd(&cntf[g], 1)] = e;
            } else {
                unsigned e = ((unsigned)p << 10) | (unsigned)((ly << 6) | lx);
                el[g * EDGE_CAP + atomicAdd(&cnte[g], 1)] = e;
            }
        }
    }
    // ---- init accumulators to bias ----
    for (int f = t; f < NPIX * 17; f += NTHREADS) {
        int c4 = f % 17;
        float4 v = make_float4(0.f, 0.f, 0.f, 0.f);
        if (c4 < 16) v = *(const float4*)(bias + c4 * 4);
        ((float4*)acc_s)[f] = v;
    }
    __syncthreads();

    // ---- proportional slot allocation: 16 slots over 4 groups ----
    const int nf0 = cntf[0], nf1 = cntf[1], nf2 = cntf[2], nf3 = cntf[3];
    const int ne0 = cnte[0], ne1 = cnte[1], ne2 = cnte[2], ne3 = cnte[3];
    const int w0 = 2 * nf0 + ne0, w1 = 2 * nf1 + ne1;
    const int w2 = 2 * nf2 + ne2, w3 = 2 * nf3 + ne3;
    const int W = w0 + w1 + w2 + w3;   // >= 360, never 0
    int e0 = 12 * w0 / W, e1 = 12 * w1 / W, e2 = 12 * w2 / W, e3 = 12 * w3 / W;
    int rem = 12 - (e0 + e1 + e2 + e3);
    // rank remainders (descending, ties by index) and give +1 to top `rem`
    int f0 = 12 * w0 - e0 * W, f1 = 12 * w1 - e1 * W;
    int f2 = 12 * w2 - e2 * W, f3 = 12 * w3 - e3 * W;
    int r0 = (f1 > f0) + (f2 > f0) + (f3 > f0);
    int r1 = (f0 >= f1) + (f2 > f1) + (f3 > f1);
    int r2 = (f0 >= f2) + (f1 >= f2) + (f3 > f2);
    int r3 = (f0 >= f3) + (f1 >= f3) + (f2 >= f3);
    int s0 = 1 + e0 + (r0 < rem), s1 = 1 + e1 + (r1 < rem);
    int s2 = 1 + e2 + (r2 < rem), s3 = 1 + e3 + (r3 < rem);
    const int S1 = s0, S2 = s0 + s1, S3 = s0 + s1 + s2;

    const int k = t >> 4;  // slot id 0..15
    const int g = (k >= S1) + (k >= S2) + (k >= S3);
    const int rank = k - (g == 0 ? 0 : g == 1 ? S1 : g == 2 ? S2 : S3);
    const int sg = (g == 0 ? s0 : g == 1 ? s1 : g == 2 ? s2 : s3);
    const int nf = (g == 0 ? nf0 : g == 1 ? nf1 : g == 2 ? nf2 : nf3);
    const int ne = (g == 0 ? ne0 : g == 1 ? ne1 : g == 2 ? ne2 : ne3);
    const unsigned* Lf = fl + g * FULL_CAP;
    const unsigned* Le = el + g * EDGE_CAP;

    const int ocg = t & 15;
    const char* xb = (const char*)x_s;
    char* accb = (char*)acc_s + ocg * 16;

#pragma unroll 1
    for (int tap = 0; tap < 9; tap++) {
        const int ky = tap / 3;
        const int kx = tap - ky * 3;
        const int tapoffB = (ky * TX + kx) * (ACC_STRIDE * 4);

        // this slot's (tap, g) weight slice: 16 LDG.128 (L1-resident hot set)
        ull wA[8], wB[8], wC[8], wD[8];
        const ulonglong2* wq =
            (const ulonglong2*)(g_wp + (tap * 4 + g) * 1024) + ocg;
#pragma unroll
        for (int c2 = 0; c2 < 8; c2++) {
            ulonglong2 q0 = wq[c2 * 32];
            ulonglong2 q1 = wq[c2 * 32 + 16];
            wA[c2] = q0.x; wB[c2] = q0.y;
            wC[c2] = q1.x; wD[c2] = q1.y;
        }

        // full-interior list: checkless, 2 pixels per iteration
        {
            int i = rank * 2;
            const int step = sg * 2;
            for (; i + 1 < nf; i += step) {
                unsigned u0 = Lf[i], u1 = Lf[i + 1];
                PixAcc A = pix_compute((int)(u0 >> 17),
                                       (int)(u0 & 0x1FFFF) - tapoffB,
                                       xb, accb, wA, wB, wC, wD);
                PixAcc B = pix_compute((int)(u1 >> 17),
                                       (int)(u1 & 0x1FFFF) - tapoffB,
                                       xb, accb, wA, wB, wC, wD);
                pix_commit(A);
                pix_commit(B);
            }
            if (i < nf) {
                unsigned u0 = Lf[i];
                PixAcc A = pix_compute((int)(u0 >> 17),
                                       (int)(u0 & 0x1FFFF) - tapoffB,
                                       xb, accb, wA, wB, wC, wD);
                pix_commit(A);
            }
        }
        // edge list: bounds-checked per tap
        for (int i = rank; i < ne; i += sg) {
            unsigned e = Le[i];
            int ly = (e >> 6) & 15, lx = e & 63;
            int oy = ly - ky, ox = lx - kx;
            if ((unsigned)oy < (unsigned)TY && (unsigned)ox < (unsigned)TX) {
                PixAcc A = pix_compute((int)((e >> 10) << 6),
                                       (oy * TX + ox) * (ACC_STRIDE * 4),
                                       xb, accb, wA, wB, wC, wD);
                pix_commit(A);
            }
        }
        __syncthreads();  // acc ownership handoff between taps
    }

    // ---- epilogue: maxout group selection, one thread per pixel ----
    {
        const float* ar = acc_s + t * ACC_STRIDE;
        float best = -3.4e38f;
        int bi = 0;
#pragma unroll
        for (int og = 0; og < 4; og++) {
            float m = -3.4e38f;
#pragma unroll
            for (int kk = 0; kk < 16; kk += 4) {
                float4 v = *(const float4*)(ar + og * 16 + kk);
                m = fmaxf(m, fmaxf(fmaxf(v.x, v.y), fmaxf(v.z, v.w)));
            }
            if (m > best) { best = m; bi = og; }  // first-max tie-break
        }
        int pyl = t >> 5, pxl = t & 31;
        size_t opix = ((size_t)b * 256 + (oy0 + pyl)) * 256 + (ox0 + pxl);
        float4* op = (float4*)(out + opix * 16);
        const float4* sp = (const float4*)(ar + bi * 16);
        op[0] = sp[0];
        op[1] = sp[1];
        op[2] = sp[2];
        op[3] = sp[3];
        if (write_idx) out_idx[opix] = (float)bi;
    }
}

extern "C" void kernel_launch(void* const* d_in, const int* in_sizes, int n_in,
                              void* d_out, int out_size) {
    const float* x = (const float*)d_in[0];
    const int* gi = (const int*)d_in[1];
    const float* w = (const float*)d_in[2];
    const float* bias = (const float*)d_in[3];
    float* out = (float*)d_out;

    const int n_sel = in_sizes[0];  // B*H*W*16 (sel output size)
    const int n_pix = in_sizes[1];  // B*H*W
    const int B = n_pix / (256 * 256);
    const int write_idx = (out_size >= n_sel + n_pix) ? 1 : 0;

    prepack_w<<<(36864 + 255) / 256, 256>>>(w);

    cudaFuncSetAttribute(ssconv_main, cudaFuncAttributeMaxDynamicSharedMemorySize,
                         SMEM_BYTES);
    dim3 grid(256 / TX, 256 / TY, B);
    ssconv_main<<<grid, NTHREADS, SMEM_BYTES>>>(x, gi, bias, out, out + n_sel,
                                                write_idx);
}